// round 4
// baseline (speedup 1.0000x reference)
#include <cuda_runtime.h>
#include <cstdint>

#define N_NODES 100000
#define HF 64
#define E_MAX 1600000

// ---------------- scratch (static device globals; no allocation) -------------
__device__ __align__(16) float g_hs[N_NODES * HF];   // dinv-scaled transformed features
__device__ __align__(16) float g_agg[N_NODES * HF];  // edge-aggregation accumulator
__device__ __align__(16) float g_x[N_NODES * HF];    // layer activations
__device__ float g_dinv[N_NODES];
__device__ int   g_cnt[N_NODES];
__device__ int   g_src[E_MAX];
__device__ int   g_dst[E_MAX];
__device__ int   g_is_i32;           // 1 if edge_index buffer is int32, 0 if int64

// ---------------- small prep kernels -----------------------------------------
__global__ void k_zero_cnt() {
    int i = blockIdx.x * blockDim.x + threadIdx.x;
    if (i < N_NODES) g_cnt[i] = 0;
    if (i == 0) g_is_i32 = 0;
}

// Detect dtype of the edge buffer. int64 values < 2^31 have all-zero high
// words (odd 32-bit words, little-endian). int32 data has random node ids
// there. OR-reduce any nonzero odd word into g_is_i32.
__global__ void k_detect(const int* __restrict__ ei32, int nwords) {
    int i = blockIdx.x * blockDim.x + threadIdx.x;  // check word 2i+1
    int w = 2 * i + 1;
    if (w < nwords && i < 2048) {
        if (ei32[w] != 0) atomicOr(&g_is_i32, 1);
    }
}

__global__ void k_prep(const void* __restrict__ eiv, int E) {
    const bool i32 = (g_is_i32 != 0);
    const int* __restrict__ p32 = (const int*)eiv;
    const long long* __restrict__ p64 = (const long long*)eiv;
    int stride = gridDim.x * blockDim.x;
    for (int i = blockIdx.x * blockDim.x + threadIdx.x; i < E; i += stride) {
        int s, d;
        if (i32) {
            s = p32[i];
            d = p32[E + i];
        } else {
            s = (int)p64[i];
            d = (int)p64[(size_t)E + i];
        }
        // clamp: never trap on a wrong dtype theory — fail with rel_err instead
        if ((unsigned)s >= N_NODES) s = 0;
        if ((unsigned)d >= N_NODES) d = 0;
        g_src[i] = s;
        g_dst[i] = d;
        atomicAdd(&g_cnt[d], 1);
    }
}

__global__ void k_dinv() {
    int i = blockIdx.x * blockDim.x + threadIdx.x;
    if (i < N_NODES) g_dinv[i] = rsqrtf((float)g_cnt[i] + 1.0f);
}

__global__ void k_zero_agg() {
    int n4 = N_NODES * HF / 4;
    int stride = gridDim.x * blockDim.x;
    float4 z = make_float4(0.f, 0.f, 0.f, 0.f);
    for (int i = blockIdx.x * blockDim.x + threadIdx.x; i < n4; i += stride)
        ((float4*)g_agg)[i] = z;
}

// ---------------- GEMM: g_hs = dinv[m] * (Xsrc[N,K] @ W[K,64]) ---------------
// FROM_GX=false : X = external pointer (node_features)
// FROM_GX=true  : X = g_x (device symbol, resolved in device code)
template <int K, bool FROM_GX>
__global__ __launch_bounds__(256)
void k_gemm(const float* __restrict__ Xext, const float* __restrict__ W)
{
    const float* __restrict__ X = FROM_GX ? (const float*)g_x : Xext;

    constexpr int BM = 128, BN = 64, BK = 16;
    constexpr int XS = BM + 4;  // 132
    __shared__ float sbuf[BK * XS + BK * BN];
    float* Xs = sbuf;                // [BK][XS]
    float* Ws = sbuf + BK * XS;      // [BK][BN]

    const int tid = threadIdx.x;
    const int m0  = blockIdx.x * BM;
    const int tm  = tid >> 4;   // 0..15 -> rows 8*tm..8*tm+7
    const int tn  = tid & 15;   // 0..15 -> cols 4*tn..4*tn+3

    float acc[8][4];
#pragma unroll
    for (int r = 0; r < 8; r++)
#pragma unroll
        for (int c = 0; c < 4; c++) acc[r][c] = 0.f;

    for (int k0 = 0; k0 < K; k0 += BK) {
#pragma unroll
        for (int p = 0; p < 2; p++) {
            int idx = tid + p * 256;
            int m = idx >> 2, kq = idx & 3;
            int gm = m0 + m;
            float4 v = make_float4(0.f, 0.f, 0.f, 0.f);
            if (gm < N_NODES)
                v = *(const float4*)(X + (size_t)gm * K + k0 + 4 * kq);
            Xs[(4 * kq + 0) * XS + m] = v.x;
            Xs[(4 * kq + 1) * XS + m] = v.y;
            Xs[(4 * kq + 2) * XS + m] = v.z;
            Xs[(4 * kq + 3) * XS + m] = v.w;
        }
        {
            int kk = tid >> 4, nq = tid & 15;
            *(float4*)(Ws + kk * BN + 4 * nq) =
                *(const float4*)(W + (size_t)(k0 + kk) * BN + 4 * nq);
        }
        __syncthreads();
#pragma unroll
        for (int kk = 0; kk < BK; kk++) {
            float a[8], b[4];
            *(float4*)&a[0] = *(const float4*)&Xs[kk * XS + 8 * tm];
            *(float4*)&a[4] = *(const float4*)&Xs[kk * XS + 8 * tm + 4];
            *(float4*)&b[0] = *(const float4*)&Ws[kk * BN + 4 * tn];
#pragma unroll
            for (int r = 0; r < 8; r++)
#pragma unroll
                for (int c = 0; c < 4; c++)
                    acc[r][c] = fmaf(a[r], b[c], acc[r][c]);
        }
        __syncthreads();
    }

#pragma unroll
    for (int r = 0; r < 8; r++) {
        int m = m0 + 8 * tm + r;
        if (m < N_NODES) {
            float dv = g_dinv[m];
            float4 o = make_float4(dv * acc[r][0], dv * acc[r][1],
                                   dv * acc[r][2], dv * acc[r][3]);
            *(float4*)(g_hs + (size_t)m * BN + 4 * tn) = o;
        }
    }
}

// ---------------- head GEMM: out[f*N+m] = sigmoid(g_x @ Wl + bl) -------------
__global__ __launch_bounds__(256)
void k_gemm_head(const float* __restrict__ W, const float* __restrict__ bias,
                 float* __restrict__ out)
{
    constexpr int K = 64, BM = 128, BN = 64, BK = 16;
    constexpr int XS = BM + 4;
    constexpr int SS = BN + 4;
    __shared__ float sbuf[BM * SS];  // covers both phases
    float* Xs = sbuf;
    float* Ws = sbuf + BK * XS;

    const int tid = threadIdx.x;
    const int m0  = blockIdx.x * BM;
    const int tm  = tid >> 4;
    const int tn  = tid & 15;

    float acc[8][4];
#pragma unroll
    for (int r = 0; r < 8; r++)
#pragma unroll
        for (int c = 0; c < 4; c++) acc[r][c] = 0.f;

    for (int k0 = 0; k0 < K; k0 += BK) {
#pragma unroll
        for (int p = 0; p < 2; p++) {
            int idx = tid + p * 256;
            int m = idx >> 2, kq = idx & 3;
            int gm = m0 + m;
            float4 v = make_float4(0.f, 0.f, 0.f, 0.f);
            if (gm < N_NODES)
                v = *(const float4*)(g_x + (size_t)gm * K + k0 + 4 * kq);
            Xs[(4 * kq + 0) * XS + m] = v.x;
            Xs[(4 * kq + 1) * XS + m] = v.y;
            Xs[(4 * kq + 2) * XS + m] = v.z;
            Xs[(4 * kq + 3) * XS + m] = v.w;
        }
        {
            int kk = tid >> 4, nq = tid & 15;
            *(float4*)(Ws + kk * BN + 4 * nq) =
                *(const float4*)(W + (size_t)(k0 + kk) * BN + 4 * nq);
        }
        __syncthreads();
#pragma unroll
        for (int kk = 0; kk < BK; kk++) {
            float a[8], b[4];
            *(float4*)&a[0] = *(const float4*)&Xs[kk * XS + 8 * tm];
            *(float4*)&a[4] = *(const float4*)&Xs[kk * XS + 8 * tm + 4];
            *(float4*)&b[0] = *(const float4*)&Ws[kk * BN + 4 * tn];
#pragma unroll
            for (int r = 0; r < 8; r++)
#pragma unroll
                for (int c = 0; c < 4; c++)
                    acc[r][c] = fmaf(a[r], b[c], acc[r][c]);
        }
        __syncthreads();
    }

    float b4[4];
    *(float4*)b4 = *(const float4*)(bias + 4 * tn);
#pragma unroll
    for (int r = 0; r < 8; r++) {
        int mloc = 8 * tm + r;
        float4 v;
        float t;
        t = acc[r][0] + b4[0]; v.x = 1.f / (1.f + __expf(-t));
        t = acc[r][1] + b4[1]; v.y = 1.f / (1.f + __expf(-t));
        t = acc[r][2] + b4[2]; v.z = 1.f / (1.f + __expf(-t));
        t = acc[r][3] + b4[3]; v.w = 1.f / (1.f + __expf(-t));
        *(float4*)&sbuf[mloc * SS + 4 * tn] = v;
    }
    __syncthreads();
    for (int idx = tid; idx < BM * BN; idx += 256) {
        int f = idx >> 7;        // 0..63
        int mloc = idx & 127;    // 0..127
        int m = m0 + mloc;
        if (m < N_NODES)
            out[(size_t)f * N_NODES + m] = sbuf[mloc * SS + f];
    }
}

// ---------------- edge scatter: agg[dst] += hs[src] --------------------------
__global__ __launch_bounds__(256)
void k_scatter(int E)
{
    int t = blockIdx.x * blockDim.x + threadIdx.x;
    int stride = gridDim.x * blockDim.x;
    int nitems = E * 16;
    for (int item = t; item < nitems; item += stride) {
        int e = item >> 4;
        int l = item & 15;
        int s = g_src[e];
        int d = g_dst[e];
        float4 v = *(const float4*)(g_hs + (size_t)s * HF + 4 * l);
        float* p = g_agg + (size_t)d * HF + 4 * l;
        atomicAdd(p + 0, v.x);
        atomicAdd(p + 1, v.y);
        atomicAdd(p + 2, v.z);
        atomicAdd(p + 3, v.w);
    }
}

// ---------------- finalize: g_x = relu(dinv*(agg+hs) + b) --------------------
__global__ __launch_bounds__(256)
void k_finalize(const float* __restrict__ bias)
{
    int n4 = N_NODES * (HF / 4);
    int stride = gridDim.x * blockDim.x;
    for (int idx = blockIdx.x * blockDim.x + threadIdx.x; idx < n4; idx += stride) {
        int i = idx >> 4;
        int q = idx & 15;
        float dv = g_dinv[i];
        float4 a = ((const float4*)g_agg)[idx];
        float4 h = ((const float4*)g_hs)[idx];
        float4 b = *(const float4*)(bias + 4 * q);
        float4 o;
        o.x = fmaxf(fmaf(dv, a.x + h.x, b.x), 0.f);
        o.y = fmaxf(fmaf(dv, a.y + h.y, b.y), 0.f);
        o.z = fmaxf(fmaf(dv, a.z + h.z, b.z), 0.f);
        o.w = fmaxf(fmaf(dv, a.w + h.w, b.w), 0.f);
        ((float4*)g_x)[idx] = o;
    }
}

// ---------------- launch ------------------------------------------------------
extern "C" void kernel_launch(void* const* d_in, const int* in_sizes, int n_in,
                              void* d_out, int out_size)
{
    const float* x  = (const float*)d_in[0];
    const void*  ei = d_in[1];
    const float* W1 = (const float*)d_in[2];
    const float* b1 = (const float*)d_in[3];
    const float* W2 = (const float*)d_in[4];
    const float* b2 = (const float*)d_in[5];
    const float* Wl = (const float*)d_in[6];
    const float* bl = (const float*)d_in[7];
    float*       out = (float*)d_out;
    const int nwords = in_sizes[1];   // element count of edge_index (2*E)
    const int E = nwords / 2;

    const int nblk = (N_NODES + 255) / 256;        // 391
    const int gemm_blocks = (N_NODES + 127) / 128; // 782

    // degree / indices (dtype-robust)
    k_zero_cnt<<<nblk, 256>>>();
    k_detect<<<8, 256>>>((const int*)ei, nwords);
    k_prep<<<2048, 256>>>(ei, E);
    k_dinv<<<nblk, 256>>>();

    // ---- layer 1 ----
    k_zero_agg<<<1024, 256>>>();
    k_gemm<128, false><<<gemm_blocks, 256>>>(x, W1);
    k_scatter<<<4096, 256>>>(E);
    k_finalize<<<2048, 256>>>(b1);

    // ---- layer 2 ----
    k_zero_agg<<<1024, 256>>>();
    k_gemm<64, true><<<gemm_blocks, 256>>>(nullptr, W2);
    k_scatter<<<4096, 256>>>(E);
    k_finalize<<<2048, 256>>>(b2);

    // ---- head: sigmoid(g_x @ Wl + bl), transposed store ----
    k_gemm_head<<<gemm_blocks, 256>>>(Wl, bl, out);

    (void)n_in; (void)out_size;
}

// round 5
// speedup vs baseline: 2.7217x; 2.7217x over previous
#include <cuda_runtime.h>
#include <cstdint>

#define N_NODES 100000
#define HF 64
#define E_MAX 1600000
#define NBLK_SCAN 391            // ceil(N_NODES/256)

// ---------------- scratch (static device globals; no allocation) -------------
__device__ __align__(16) float g_hs[N_NODES * HF];   // dinv-scaled transformed features
__device__ __align__(16) float g_x[N_NODES * HF];    // layer activations
__device__ float g_dinv[N_NODES];
__device__ int   g_cnt[N_NODES];      // in-degree (no self loop)
__device__ int   g_off[N_NODES];      // CSR row offsets (exclusive prefix of cnt)
__device__ int   g_cur[N_NODES];      // fill cursors
__device__ int   g_bsum[512];         // block sums for scan
__device__ int   g_src[E_MAX];
__device__ int   g_dst[E_MAX];
__device__ int   g_csr[E_MAX];        // src ids sorted by dst
__device__ int   g_is_i32;

// ---------------- prep: decode edges, count degrees ---------------------------
__global__ void k_zero_cnt() {
    int i = blockIdx.x * blockDim.x + threadIdx.x;
    if (i < N_NODES) { g_cnt[i] = 0; g_cur[i] = 0; }
    if (i == 0) g_is_i32 = 0;
}

// int64 node-ids < 2^31 have all-zero odd 32-bit words; int32 data doesn't.
__global__ void k_detect(const int* __restrict__ ei32, int nwords) {
    int i = blockIdx.x * blockDim.x + threadIdx.x;
    int w = 2 * i + 1;
    if (w < nwords && i < 2048) {
        if (ei32[w] != 0) atomicOr(&g_is_i32, 1);
    }
}

__global__ void k_prep(const void* __restrict__ eiv, int E) {
    const bool i32 = (g_is_i32 != 0);
    const int* __restrict__ p32 = (const int*)eiv;
    const long long* __restrict__ p64 = (const long long*)eiv;
    int stride = gridDim.x * blockDim.x;
    for (int i = blockIdx.x * blockDim.x + threadIdx.x; i < E; i += stride) {
        int s, d;
        if (i32) { s = p32[i]; d = p32[E + i]; }
        else     { s = (int)p64[i]; d = (int)p64[(size_t)E + i]; }
        if ((unsigned)s >= N_NODES) s = 0;
        if ((unsigned)d >= N_NODES) d = 0;
        g_src[i] = s;
        g_dst[i] = d;
        atomicAdd(&g_cnt[d], 1);
    }
}

__global__ void k_dinv() {
    int i = blockIdx.x * blockDim.x + threadIdx.x;
    if (i < N_NODES) g_dinv[i] = rsqrtf((float)g_cnt[i] + 1.0f);
}

// ---------------- 3-phase exclusive scan of g_cnt -> g_off --------------------
__global__ __launch_bounds__(256) void k_scan1() {
    __shared__ int sh[256];
    int i = blockIdx.x * 256 + threadIdx.x;
    int c = (i < N_NODES) ? g_cnt[i] : 0;
    sh[threadIdx.x] = c;
    __syncthreads();
    // Hillis–Steele inclusive scan
    int v = c;
#pragma unroll
    for (int ofs = 1; ofs < 256; ofs <<= 1) {
        int t = (threadIdx.x >= ofs) ? sh[threadIdx.x - ofs] : 0;
        __syncthreads();
        v += t;
        sh[threadIdx.x] = v;
        __syncthreads();
    }
    if (i < N_NODES) g_off[i] = v - c;          // exclusive, block-local
    if (threadIdx.x == 255) g_bsum[blockIdx.x] = v;
}

__global__ __launch_bounds__(512) void k_scan2() {
    __shared__ int sh[512];
    int t = threadIdx.x;
    int c = (t < NBLK_SCAN) ? g_bsum[t] : 0;
    sh[t] = c;
    __syncthreads();
    int v = c;
#pragma unroll
    for (int ofs = 1; ofs < 512; ofs <<= 1) {
        int x = (t >= ofs) ? sh[t - ofs] : 0;
        __syncthreads();
        v += x;
        sh[t] = v;
        __syncthreads();
    }
    if (t < NBLK_SCAN) g_bsum[t] = v - c;       // exclusive block offsets
}

__global__ __launch_bounds__(256) void k_scan3() {
    int i = blockIdx.x * 256 + threadIdx.x;
    if (i < N_NODES) g_off[i] += g_bsum[blockIdx.x];
}

// ---------------- CSR fill: bucket src by dst ---------------------------------
__global__ __launch_bounds__(256) void k_fill(int E) {
    int stride = gridDim.x * blockDim.x;
    for (int e = blockIdx.x * blockDim.x + threadIdx.x; e < E; e += stride) {
        int d = g_dst[e];
        int pos = g_off[d] + atomicAdd(&g_cur[d], 1);
        g_csr[pos] = g_src[e];
    }
}

// ---------------- GEMM: g_hs = dinv[m] * (X[N,K] @ W[K,64]) -------------------
template <int K, bool FROM_GX>
__global__ __launch_bounds__(256)
void k_gemm(const float* __restrict__ Xext, const float* __restrict__ W)
{
    const float* __restrict__ X = FROM_GX ? (const float*)g_x : Xext;

    constexpr int BM = 128, BN = 64, BK = 16;
    constexpr int XS = BM + 4;
    __shared__ float sbuf[BK * XS + BK * BN];
    float* Xs = sbuf;
    float* Ws = sbuf + BK * XS;

    const int tid = threadIdx.x;
    const int m0  = blockIdx.x * BM;
    const int tm  = tid >> 4;
    const int tn  = tid & 15;

    float acc[8][4];
#pragma unroll
    for (int r = 0; r < 8; r++)
#pragma unroll
        for (int c = 0; c < 4; c++) acc[r][c] = 0.f;

    for (int k0 = 0; k0 < K; k0 += BK) {
#pragma unroll
        for (int p = 0; p < 2; p++) {
            int idx = tid + p * 256;
            int m = idx >> 2, kq = idx & 3;
            int gm = m0 + m;
            float4 v = make_float4(0.f, 0.f, 0.f, 0.f);
            if (gm < N_NODES)
                v = *(const float4*)(X + (size_t)gm * K + k0 + 4 * kq);
            Xs[(4 * kq + 0) * XS + m] = v.x;
            Xs[(4 * kq + 1) * XS + m] = v.y;
            Xs[(4 * kq + 2) * XS + m] = v.z;
            Xs[(4 * kq + 3) * XS + m] = v.w;
        }
        {
            int kk = tid >> 4, nq = tid & 15;
            *(float4*)(Ws + kk * BN + 4 * nq) =
                *(const float4*)(W + (size_t)(k0 + kk) * BN + 4 * nq);
        }
        __syncthreads();
#pragma unroll
        for (int kk = 0; kk < BK; kk++) {
            float a[8], b[4];
            *(float4*)&a[0] = *(const float4*)&Xs[kk * XS + 8 * tm];
            *(float4*)&a[4] = *(const float4*)&Xs[kk * XS + 8 * tm + 4];
            *(float4*)&b[0] = *(const float4*)&Ws[kk * BN + 4 * tn];
#pragma unroll
            for (int r = 0; r < 8; r++)
#pragma unroll
                for (int c = 0; c < 4; c++)
                    acc[r][c] = fmaf(a[r], b[c], acc[r][c]);
        }
        __syncthreads();
    }

#pragma unroll
    for (int r = 0; r < 8; r++) {
        int m = m0 + 8 * tm + r;
        if (m < N_NODES) {
            float dv = g_dinv[m];
            float4 o = make_float4(dv * acc[r][0], dv * acc[r][1],
                                   dv * acc[r][2], dv * acc[r][3]);
            *(float4*)(g_hs + (size_t)m * BN + 4 * tn) = o;
        }
    }
}

// ---------------- gather + finalize: g_x = relu(dinv*(Σ hs[nbr] + hs_i) + b) --
// 16 lanes per node, float4 per lane (64 features). CSR neighbor walk,
// 2-way unrolled for MLP.
__global__ __launch_bounds__(256)
void k_gather(const float* __restrict__ bias)
{
    int g = (blockIdx.x * 256 + threadIdx.x) >> 4;   // node id
    int l = threadIdx.x & 15;
    if (g >= N_NODES) return;

    const int beg = g_off[g];
    const int deg = g_cnt[g];
    const int end = beg + deg;

    // self-loop term (hs already scaled by dinv[src]; self gives dinv_i*h_i)
    float4 acc = *(const float4*)(g_hs + (size_t)g * HF + 4 * l);

    int j = beg;
    for (; j + 2 <= end; j += 2) {
        int s0 = g_csr[j];
        int s1 = g_csr[j + 1];
        float4 v0 = *(const float4*)(g_hs + (size_t)s0 * HF + 4 * l);
        float4 v1 = *(const float4*)(g_hs + (size_t)s1 * HF + 4 * l);
        acc.x += v0.x + v1.x;
        acc.y += v0.y + v1.y;
        acc.z += v0.z + v1.z;
        acc.w += v0.w + v1.w;
    }
    if (j < end) {
        int s0 = g_csr[j];
        float4 v0 = *(const float4*)(g_hs + (size_t)s0 * HF + 4 * l);
        acc.x += v0.x; acc.y += v0.y; acc.z += v0.z; acc.w += v0.w;
    }

    float dv = g_dinv[g];
    float4 b = *(const float4*)(bias + 4 * l);
    float4 o;
    o.x = fmaxf(fmaf(dv, acc.x, b.x), 0.f);
    o.y = fmaxf(fmaf(dv, acc.y, b.y), 0.f);
    o.z = fmaxf(fmaf(dv, acc.z, b.z), 0.f);
    o.w = fmaxf(fmaf(dv, acc.w, b.w), 0.f);
    *(float4*)(g_x + (size_t)g * HF + 4 * l) = o;
}

// ---------------- head GEMM: out[f*N+m] = sigmoid(g_x @ Wl + bl) -------------
__global__ __launch_bounds__(256)
void k_gemm_head(const float* __restrict__ W, const float* __restrict__ bias,
                 float* __restrict__ out)
{
    constexpr int K = 64, BM = 128, BN = 64, BK = 16;
    constexpr int XS = BM + 4;
    constexpr int SS = BN + 4;
    __shared__ float sbuf[BM * SS];
    float* Xs = sbuf;
    float* Ws = sbuf + BK * XS;

    const int tid = threadIdx.x;
    const int m0  = blockIdx.x * BM;
    const int tm  = tid >> 4;
    const int tn  = tid & 15;

    float acc[8][4];
#pragma unroll
    for (int r = 0; r < 8; r++)
#pragma unroll
        for (int c = 0; c < 4; c++) acc[r][c] = 0.f;

    for (int k0 = 0; k0 < K; k0 += BK) {
#pragma unroll
        for (int p = 0; p < 2; p++) {
            int idx = tid + p * 256;
            int m = idx >> 2, kq = idx & 3;
            int gm = m0 + m;
            float4 v = make_float4(0.f, 0.f, 0.f, 0.f);
            if (gm < N_NODES)
                v = *(const float4*)(g_x + (size_t)gm * K + k0 + 4 * kq);
            Xs[(4 * kq + 0) * XS + m] = v.x;
            Xs[(4 * kq + 1) * XS + m] = v.y;
            Xs[(4 * kq + 2) * XS + m] = v.z;
            Xs[(4 * kq + 3) * XS + m] = v.w;
        }
        {
            int kk = tid >> 4, nq = tid & 15;
            *(float4*)(Ws + kk * BN + 4 * nq) =
                *(const float4*)(W + (size_t)(k0 + kk) * BN + 4 * nq);
        }
        __syncthreads();
#pragma unroll
        for (int kk = 0; kk < BK; kk++) {
            float a[8], b[4];
            *(float4*)&a[0] = *(const float4*)&Xs[kk * XS + 8 * tm];
            *(float4*)&a[4] = *(const float4*)&Xs[kk * XS + 8 * tm + 4];
            *(float4*)&b[0] = *(const float4*)&Ws[kk * BN + 4 * tn];
#pragma unroll
            for (int r = 0; r < 8; r++)
#pragma unroll
                for (int c = 0; c < 4; c++)
                    acc[r][c] = fmaf(a[r], b[c], acc[r][c]);
        }
        __syncthreads();
    }

    float b4[4];
    *(float4*)b4 = *(const float4*)(bias + 4 * tn);
#pragma unroll
    for (int r = 0; r < 8; r++) {
        int mloc = 8 * tm + r;
        float4 v;
        float t;
        t = acc[r][0] + b4[0]; v.x = 1.f / (1.f + __expf(-t));
        t = acc[r][1] + b4[1]; v.y = 1.f / (1.f + __expf(-t));
        t = acc[r][2] + b4[2]; v.z = 1.f / (1.f + __expf(-t));
        t = acc[r][3] + b4[3]; v.w = 1.f / (1.f + __expf(-t));
        *(float4*)&sbuf[mloc * SS + 4 * tn] = v;
    }
    __syncthreads();
    for (int idx = tid; idx < BM * BN; idx += 256) {
        int f = idx >> 7;
        int mloc = idx & 127;
        int m = m0 + mloc;
        if (m < N_NODES)
            out[(size_t)f * N_NODES + m] = sbuf[mloc * SS + f];
    }
}

// ---------------- launch ------------------------------------------------------
extern "C" void kernel_launch(void* const* d_in, const int* in_sizes, int n_in,
                              void* d_out, int out_size)
{
    const float* x  = (const float*)d_in[0];
    const void*  ei = d_in[1];
    const float* W1 = (const float*)d_in[2];
    const float* b1 = (const float*)d_in[3];
    const float* W2 = (const float*)d_in[4];
    const float* b2 = (const float*)d_in[5];
    const float* Wl = (const float*)d_in[6];
    const float* bl = (const float*)d_in[7];
    float*       out = (float*)d_out;
    const int nwords = in_sizes[1];
    const int E = nwords / 2;

    const int nblk = NBLK_SCAN;                      // 391
    const int gemm_blocks = (N_NODES + 127) / 128;   // 782
    const int gather_blocks = (N_NODES * 16 + 255) / 256; // 6250

    // ---- graph prep: decode, degrees, CSR ----
    k_zero_cnt<<<nblk, 256>>>();
    k_detect<<<8, 256>>>((const int*)ei, nwords);
    k_prep<<<2048, 256>>>(ei, E);
    k_dinv<<<nblk, 256>>>();
    k_scan1<<<nblk, 256>>>();
    k_scan2<<<1, 512>>>();
    k_scan3<<<nblk, 256>>>();
    k_fill<<<2048, 256>>>(E);

    // ---- layer 1 ----
    k_gemm<128, false><<<gemm_blocks, 256>>>(x, W1);
    k_gather<<<gather_blocks, 256>>>(b1);

    // ---- layer 2 ----
    k_gemm<64, true><<<gemm_blocks, 256>>>(nullptr, W2);
    k_gather<<<gather_blocks, 256>>>(b2);

    // ---- head: sigmoid(g_x @ Wl + bl), transposed store ----
    k_gemm_head<<<gemm_blocks, 256>>>(Wl, bl, out);

    (void)n_in; (void)out_size;
}

// round 6
// speedup vs baseline: 2.8063x; 1.0311x over previous
#include <cuda_runtime.h>
#include <cstdint>

#define N_NODES 100000
#define HF 64
#define E_MAX 1600000
#define NBLK_SCAN 391            // ceil(N_NODES/256)

// ---- Blackwell packed f32x2 helpers -----------------------------------------
#define FMA2(d, a, b) \
    asm("fma.rn.f32x2 %0, %1, %2, %0;" : "+l"(d) : "l"(a), "l"(b))
#define PACK2(v, lo, hi) \
    asm("mov.b64 %0, {%1, %2};" : "=l"(v) : "f"(lo), "f"(hi))
#define UNPACK2(lo, hi, v) \
    asm("mov.b64 {%0, %1}, %2;" : "=f"(lo), "=f"(hi) : "l"(v))

// ---------------- scratch (static device globals; no allocation) -------------
__device__ __align__(16) float g_hs[N_NODES * HF];   // dinv-scaled transformed features
__device__ __align__(16) float g_x[N_NODES * HF];    // layer activations
__device__ float g_dinv[N_NODES];
__device__ int   g_cnt[N_NODES];      // in-degree (no self loop)
__device__ int   g_off[N_NODES];      // CSR row offsets (exclusive prefix of cnt)
__device__ int   g_cur[N_NODES];      // fill cursors
__device__ int   g_bsum[512];         // block sums for scan
__device__ int   g_csr[E_MAX];        // src ids sorted by dst
__device__ int   g_is_i32;

// ---------------- prep: decode edges, count degrees ---------------------------
__global__ void k_zero_cnt() {
    int i = blockIdx.x * blockDim.x + threadIdx.x;
    if (i < N_NODES) { g_cnt[i] = 0; g_cur[i] = 0; }
    if (i == 0) g_is_i32 = 0;
}

// int64 node-ids < 2^31 have all-zero odd 32-bit words; int32 data doesn't.
__global__ void k_detect(const int* __restrict__ ei32, int nwords) {
    int i = blockIdx.x * blockDim.x + threadIdx.x;
    int w = 2 * i + 1;
    if (w < nwords && i < 2048) {
        if (ei32[w] != 0) atomicOr(&g_is_i32, 1);
    }
}

__global__ void k_prep(const void* __restrict__ eiv, int E) {
    const bool i32 = (g_is_i32 != 0);
    const int* __restrict__ p32 = (const int*)eiv;
    const long long* __restrict__ p64 = (const long long*)eiv;
    int stride = gridDim.x * blockDim.x;
    for (int i = blockIdx.x * blockDim.x + threadIdx.x; i < E; i += stride) {
        int d = i32 ? p32[E + i] : (int)p64[(size_t)E + i];
        if ((unsigned)d >= N_NODES) d = 0;
        atomicAdd(&g_cnt[d], 1);
    }
}

__global__ void k_dinv() {
    int i = blockIdx.x * blockDim.x + threadIdx.x;
    if (i < N_NODES) g_dinv[i] = rsqrtf((float)g_cnt[i] + 1.0f);
}

// ---------------- 3-phase exclusive scan of g_cnt -> g_off --------------------
__global__ __launch_bounds__(256) void k_scan1() {
    __shared__ int sh[256];
    int i = blockIdx.x * 256 + threadIdx.x;
    int c = (i < N_NODES) ? g_cnt[i] : 0;
    sh[threadIdx.x] = c;
    __syncthreads();
    int v = c;
#pragma unroll
    for (int ofs = 1; ofs < 256; ofs <<= 1) {
        int t = (threadIdx.x >= ofs) ? sh[threadIdx.x - ofs] : 0;
        __syncthreads();
        v += t;
        sh[threadIdx.x] = v;
        __syncthreads();
    }
    if (i < N_NODES) g_off[i] = v - c;
    if (threadIdx.x == 255) g_bsum[blockIdx.x] = v;
}

__global__ __launch_bounds__(512) void k_scan2() {
    __shared__ int sh[512];
    int t = threadIdx.x;
    int c = (t < NBLK_SCAN) ? g_bsum[t] : 0;
    sh[t] = c;
    __syncthreads();
    int v = c;
#pragma unroll
    for (int ofs = 1; ofs < 512; ofs <<= 1) {
        int x = (t >= ofs) ? sh[t - ofs] : 0;
        __syncthreads();
        v += x;
        sh[t] = v;
        __syncthreads();
    }
    if (t < NBLK_SCAN) g_bsum[t] = v - c;
}

__global__ __launch_bounds__(256) void k_scan3() {
    int i = blockIdx.x * 256 + threadIdx.x;
    if (i < N_NODES) g_off[i] += g_bsum[blockIdx.x];
}

// ---------------- CSR fill: bucket src by dst (re-decode from input) ----------
__global__ __launch_bounds__(256) void k_fill(const void* __restrict__ eiv, int E) {
    const bool i32 = (g_is_i32 != 0);
    const int* __restrict__ p32 = (const int*)eiv;
    const long long* __restrict__ p64 = (const long long*)eiv;
    int stride = gridDim.x * blockDim.x;
    for (int e = blockIdx.x * blockDim.x + threadIdx.x; e < E; e += stride) {
        int s, d;
        if (i32) { s = p32[e]; d = p32[E + e]; }
        else     { s = (int)p64[e]; d = (int)p64[(size_t)E + e]; }
        if ((unsigned)s >= N_NODES) s = 0;
        if ((unsigned)d >= N_NODES) d = 0;
        int pos = g_off[d] + atomicAdd(&g_cur[d], 1);
        g_csr[pos] = s;
    }
}

// ---------------- GEMM: g_hs = dinv[m] * (X[N,K] @ W[K,64]) -------------------
// inner product via packed fma.rn.f32x2: rows paired into 64-bit accumulators
template <int K, bool FROM_GX>
__global__ __launch_bounds__(256)
void k_gemm(const float* __restrict__ Xext, const float* __restrict__ W)
{
    const float* __restrict__ X = FROM_GX ? (const float*)g_x : Xext;

    constexpr int BM = 128, BN = 64, BK = 16;
    constexpr int XS = BM + 4;
    __shared__ float sbuf[BK * XS + BK * BN];
    float* Xs = sbuf;
    float* Ws = sbuf + BK * XS;

    const int tid = threadIdx.x;
    const int m0  = blockIdx.x * BM;
    const int tm  = tid >> 4;
    const int tn  = tid & 15;

    unsigned long long acc2[4][4];   // [row-pair][col]: lo=row 2rp, hi=row 2rp+1
#pragma unroll
    for (int rp = 0; rp < 4; rp++)
#pragma unroll
        for (int c = 0; c < 4; c++) acc2[rp][c] = 0ull;

    for (int k0 = 0; k0 < K; k0 += BK) {
#pragma unroll
        for (int p = 0; p < 2; p++) {
            int idx = tid + p * 256;
            int m = idx >> 2, kq = idx & 3;
            int gm = m0 + m;
            float4 v = make_float4(0.f, 0.f, 0.f, 0.f);
            if (gm < N_NODES)
                v = *(const float4*)(X + (size_t)gm * K + k0 + 4 * kq);
            Xs[(4 * kq + 0) * XS + m] = v.x;
            Xs[(4 * kq + 1) * XS + m] = v.y;
            Xs[(4 * kq + 2) * XS + m] = v.z;
            Xs[(4 * kq + 3) * XS + m] = v.w;
        }
        {
            int kk = tid >> 4, nq = tid & 15;
            *(float4*)(Ws + kk * BN + 4 * nq) =
                *(const float4*)(W + (size_t)(k0 + kk) * BN + 4 * nq);
        }
        __syncthreads();
#pragma unroll
        for (int kk = 0; kk < BK; kk++) {
            float a[8], b[4];
            *(float4*)&a[0] = *(const float4*)&Xs[kk * XS + 8 * tm];
            *(float4*)&a[4] = *(const float4*)&Xs[kk * XS + 8 * tm + 4];
            *(float4*)&b[0] = *(const float4*)&Ws[kk * BN + 4 * tn];
            unsigned long long a2[4], b2[4];
            PACK2(a2[0], a[0], a[1]);
            PACK2(a2[1], a[2], a[3]);
            PACK2(a2[2], a[4], a[5]);
            PACK2(a2[3], a[6], a[7]);
            PACK2(b2[0], b[0], b[0]);
            PACK2(b2[1], b[1], b[1]);
            PACK2(b2[2], b[2], b[2]);
            PACK2(b2[3], b[3], b[3]);
#pragma unroll
            for (int rp = 0; rp < 4; rp++)
#pragma unroll
                for (int c = 0; c < 4; c++)
                    FMA2(acc2[rp][c], a2[rp], b2[c]);
        }
        __syncthreads();
    }

#pragma unroll
    for (int rp = 0; rp < 4; rp++) {
        float lo[4], hi[4];
#pragma unroll
        for (int c = 0; c < 4; c++) UNPACK2(lo[c], hi[c], acc2[rp][c]);
        int mA = m0 + 8 * tm + 2 * rp;
        int mB = mA + 1;
        if (mA < N_NODES) {
            float dv = g_dinv[mA];
            float4 o = make_float4(dv * lo[0], dv * lo[1], dv * lo[2], dv * lo[3]);
            *(float4*)(g_hs + (size_t)mA * BN + 4 * tn) = o;
        }
        if (mB < N_NODES) {
            float dv = g_dinv[mB];
            float4 o = make_float4(dv * hi[0], dv * hi[1], dv * hi[2], dv * hi[3]);
            *(float4*)(g_hs + (size_t)mB * BN + 4 * tn) = o;
        }
    }
}

// ---------------- gather + finalize: g_x = relu(dinv*(Σ hs[nbr] + hs_i) + b) --
__global__ __launch_bounds__(256)
void k_gather(const float* __restrict__ bias)
{
    int g = (blockIdx.x * 256 + threadIdx.x) >> 4;   // node id
    int l = threadIdx.x & 15;
    if (g >= N_NODES) return;

    const int beg = g_off[g];
    const int deg = g_cnt[g];
    const int end = beg + deg;

    float4 acc = *(const float4*)(g_hs + (size_t)g * HF + 4 * l);

    int j = beg;
    for (; j + 2 <= end; j += 2) {
        int s0 = g_csr[j];
        int s1 = g_csr[j + 1];
        float4 v0 = *(const float4*)(g_hs + (size_t)s0 * HF + 4 * l);
        float4 v1 = *(const float4*)(g_hs + (size_t)s1 * HF + 4 * l);
        acc.x += v0.x + v1.x;
        acc.y += v0.y + v1.y;
        acc.z += v0.z + v1.z;
        acc.w += v0.w + v1.w;
    }
    if (j < end) {
        int s0 = g_csr[j];
        float4 v0 = *(const float4*)(g_hs + (size_t)s0 * HF + 4 * l);
        acc.x += v0.x; acc.y += v0.y; acc.z += v0.z; acc.w += v0.w;
    }

    float dv = g_dinv[g];
    float4 b = *(const float4*)(bias + 4 * l);
    float4 o;
    o.x = fmaxf(fmaf(dv, acc.x, b.x), 0.f);
    o.y = fmaxf(fmaf(dv, acc.y, b.y), 0.f);
    o.z = fmaxf(fmaf(dv, acc.z, b.z), 0.f);
    o.w = fmaxf(fmaf(dv, acc.w, b.w), 0.f);
    *(float4*)(g_x + (size_t)g * HF + 4 * l) = o;
}

// ---------------- head GEMM: out[f*N+m] = sigmoid(g_x @ Wl + bl) -------------
__global__ __launch_bounds__(256)
void k_gemm_head(const float* __restrict__ W, const float* __restrict__ bias,
                 float* __restrict__ out)
{
    constexpr int K = 64, BM = 128, BN = 64, BK = 16;
    constexpr int XS = BM + 4;
    constexpr int SS = BN + 4;
    __shared__ float sbuf[BM * SS];
    float* Xs = sbuf;
    float* Ws = sbuf + BK * XS;

    const int tid = threadIdx.x;
    const int m0  = blockIdx.x * BM;
    const int tm  = tid >> 4;
    const int tn  = tid & 15;

    unsigned long long acc2[4][4];
#pragma unroll
    for (int rp = 0; rp < 4; rp++)
#pragma unroll
        for (int c = 0; c < 4; c++) acc2[rp][c] = 0ull;

    for (int k0 = 0; k0 < K; k0 += BK) {
#pragma unroll
        for (int p = 0; p < 2; p++) {
            int idx = tid + p * 256;
            int m = idx >> 2, kq = idx & 3;
            int gm = m0 + m;
            float4 v = make_float4(0.f, 0.f, 0.f, 0.f);
            if (gm < N_NODES)
                v = *(const float4*)(g_x + (size_t)gm * K + k0 + 4 * kq);
            Xs[(4 * kq + 0) * XS + m] = v.x;
            Xs[(4 * kq + 1) * XS + m] = v.y;
            Xs[(4 * kq + 2) * XS + m] = v.z;
            Xs[(4 * kq + 3) * XS + m] = v.w;
        }
        {
            int kk = tid >> 4, nq = tid & 15;
            *(float4*)(Ws + kk * BN + 4 * nq) =
                *(const float4*)(W + (size_t)(k0 + kk) * BN + 4 * nq);
        }
        __syncthreads();
#pragma unroll
        for (int kk = 0; kk < BK; kk++) {
            float a[8], b[4];
            *(float4*)&a[0] = *(const float4*)&Xs[kk * XS + 8 * tm];
            *(float4*)&a[4] = *(const float4*)&Xs[kk * XS + 8 * tm + 4];
            *(float4*)&b[0] = *(const float4*)&Ws[kk * BN + 4 * tn];
            unsigned long long a2[4], b2[4];
            PACK2(a2[0], a[0], a[1]);
            PACK2(a2[1], a[2], a[3]);
            PACK2(a2[2], a[4], a[5]);
            PACK2(a2[3], a[6], a[7]);
            PACK2(b2[0], b[0], b[0]);
            PACK2(b2[1], b[1], b[1]);
            PACK2(b2[2], b[2], b[2]);
            PACK2(b2[3], b[3], b[3]);
#pragma unroll
            for (int rp = 0; rp < 4; rp++)
#pragma unroll
                for (int c = 0; c < 4; c++)
                    FMA2(acc2[rp][c], a2[rp], b2[c]);
        }
        __syncthreads();
    }

    float b4[4];
    *(float4*)b4 = *(const float4*)(bias + 4 * tn);
#pragma unroll
    for (int rp = 0; rp < 4; rp++) {
        float lo[4], hi[4];
#pragma unroll
        for (int c = 0; c < 4; c++) UNPACK2(lo[c], hi[c], acc2[rp][c]);
        int mlocA = 8 * tm + 2 * rp;
        float4 vA, vB;
        float t;
        t = lo[0] + b4[0]; vA.x = 1.f / (1.f + __expf(-t));
        t = lo[1] + b4[1]; vA.y = 1.f / (1.f + __expf(-t));
        t = lo[2] + b4[2]; vA.z = 1.f / (1.f + __expf(-t));
        t = lo[3] + b4[3]; vA.w = 1.f / (1.f + __expf(-t));
        t = hi[0] + b4[0]; vB.x = 1.f / (1.f + __expf(-t));
        t = hi[1] + b4[1]; vB.y = 1.f / (1.f + __expf(-t));
        t = hi[2] + b4[2]; vB.z = 1.f / (1.f + __expf(-t));
        t = hi[3] + b4[3]; vB.w = 1.f / (1.f + __expf(-t));
        *(float4*)&sbuf[mlocA * SS + 4 * tn] = vA;
        *(float4*)&sbuf[(mlocA + 1) * SS + 4 * tn] = vB;
    }
    __syncthreads();
    for (int idx = tid; idx < BM * BN; idx += 256) {
        int f = idx >> 7;
        int mloc = idx & 127;
        int m = m0 + mloc;
        if (m < N_NODES)
            out[(size_t)f * N_NODES + m] = sbuf[mloc * SS + f];
    }
}

// ---------------- launch ------------------------------------------------------
extern "C" void kernel_launch(void* const* d_in, const int* in_sizes, int n_in,
                              void* d_out, int out_size)
{
    const float* x  = (const float*)d_in[0];
    const void*  ei = d_in[1];
    const float* W1 = (const float*)d_in[2];
    const float* b1 = (const float*)d_in[3];
    const float* W2 = (const float*)d_in[4];
    const float* b2 = (const float*)d_in[5];
    const float* Wl = (const float*)d_in[6];
    const float* bl = (const float*)d_in[7];
    float*       out = (float*)d_out;
    const int nwords = in_sizes[1];
    const int E = nwords / 2;

    const int nblk = NBLK_SCAN;                      // 391
    const int gemm_blocks = (N_NODES + 127) / 128;   // 782
    const int gather_blocks = (N_NODES * 16 + 255) / 256; // 6250

    // ---- graph prep: decode, degrees, CSR ----
    k_zero_cnt<<<nblk, 256>>>();
    k_detect<<<8, 256>>>((const int*)ei, nwords);
    k_prep<<<2048, 256>>>(ei, E);
    k_dinv<<<nblk, 256>>>();
    k_scan1<<<nblk, 256>>>();
    k_scan2<<<1, 512>>>();
    k_scan3<<<nblk, 256>>>();
    k_fill<<<2048, 256>>>(ei, E);

    // ---- layer 1 ----
    k_gemm<128, false><<<gemm_blocks, 256>>>(x, W1);
    k_gather<<<gather_blocks, 256>>>(b1);

    // ---- layer 2 ----
    k_gemm<64, true><<<gemm_blocks, 256>>>(nullptr, W2);
    k_gather<<<gather_blocks, 256>>>(b2);

    // ---- head: sigmoid(g_x @ Wl + bl), transposed store ----
    k_gemm_head<<<gemm_blocks, 256>>>(Wl, bl, out);

    (void)n_in; (void)out_size;
}

// round 7
// speedup vs baseline: 3.0515x; 1.0874x over previous
#include <cuda_runtime.h>
#include <cuda_fp16.h>
#include <cstdint>

#define N_NODES 100000
#define HF 64
#define E_MAX 1600000
#define NBLK_SCAN 391            // ceil(N_NODES/256)

// ---- packed f32x2 helpers (issue-slot savers; rt ~4 on B300) -----------------
#define FMA2(d, a, b) \
    asm("fma.rn.f32x2 %0, %1, %2, %0;" : "+l"(d) : "l"(a), "l"(b))
#define PACK2(v, lo, hi) \
    asm("mov.b64 %0, {%1, %2};" : "=l"(v) : "f"(lo), "f"(hi))
#define UNPACK2(lo, hi, v) \
    asm("mov.b64 {%0, %1}, %2;" : "=f"(lo), "=f"(hi) : "l"(v))

// ---------------- scratch (static device globals; no allocation) -------------
__device__ __align__(16) __half g_hs[N_NODES * HF];  // dinv-scaled features, fp16
__device__ __align__(16) float  g_x[N_NODES * HF];   // layer activations, fp32
__device__ float g_dinv[N_NODES];
__device__ int   g_cnt[N_NODES];      // in-degree (no self loop)
__device__ int   g_off[N_NODES];      // block-local exclusive prefix of cnt
__device__ int   g_cur[N_NODES];      // fill cursors
__device__ int   g_bsum[512];         // per-block offsets (final after scan2)
__device__ int   g_csr[E_MAX];        // src ids sorted by dst
__device__ int   g_is_i32 = 0;        // monotone OR; deterministic across replays

// ---------------- prep -------------------------------------------------------
// zero counters + dtype sniff in one kernel (disjoint memory, no race)
__global__ void k_init(const int* __restrict__ ei32, int nwords) {
    int i = blockIdx.x * 256 + threadIdx.x;
    if (i < N_NODES) { g_cnt[i] = 0; g_cur[i] = 0; }
    int w = 2 * i + 1;   // odd words: int64 high-halves are 0, int32 data isn't
    if (i < 2048 && w < nwords) {
        if (ei32[w] != 0) atomicOr(&g_is_i32, 1);
    }
}

__global__ void k_prep(const void* __restrict__ eiv, int E) {
    const bool i32 = (g_is_i32 != 0);
    const int* __restrict__ p32 = (const int*)eiv;
    const long long* __restrict__ p64 = (const long long*)eiv;
    int stride = gridDim.x * blockDim.x;
    for (int i = blockIdx.x * blockDim.x + threadIdx.x; i < E; i += stride) {
        int d = i32 ? p32[E + i] : (int)p64[(size_t)E + i];
        if ((unsigned)d >= N_NODES) d = 0;
        atomicAdd(&g_cnt[d], 1);
    }
}

// scan1: block-local exclusive scan of g_cnt; also emits dinv and block sums
__global__ __launch_bounds__(256) void k_scan1() {
    __shared__ int sh[256];
    int i = blockIdx.x * 256 + threadIdx.x;
    int c = (i < N_NODES) ? g_cnt[i] : 0;
    sh[threadIdx.x] = c;
    __syncthreads();
    int v = c;
#pragma unroll
    for (int ofs = 1; ofs < 256; ofs <<= 1) {
        int t = (threadIdx.x >= ofs) ? sh[threadIdx.x - ofs] : 0;
        __syncthreads();
        v += t;
        sh[threadIdx.x] = v;
        __syncthreads();
    }
    if (i < N_NODES) {
        g_off[i] = v - c;
        g_dinv[i] = rsqrtf((float)c + 1.0f);
    }
    if (threadIdx.x == 255) g_bsum[blockIdx.x] = v;
}

// scan2: exclusive scan of the 391 block sums (final per-block base offsets)
__global__ __launch_bounds__(512) void k_scan2() {
    __shared__ int sh[512];
    int t = threadIdx.x;
    int c = (t < NBLK_SCAN) ? g_bsum[t] : 0;
    sh[t] = c;
    __syncthreads();
    int v = c;
#pragma unroll
    for (int ofs = 1; ofs < 512; ofs <<= 1) {
        int x = (t >= ofs) ? sh[t - ofs] : 0;
        __syncthreads();
        v += x;
        sh[t] = v;
        __syncthreads();
    }
    if (t < NBLK_SCAN) g_bsum[t] = v - c;
}

// CSR fill: final offset = g_off[d] + g_bsum[d>>8]
__global__ __launch_bounds__(256) void k_fill(const void* __restrict__ eiv, int E) {
    const bool i32 = (g_is_i32 != 0);
    const int* __restrict__ p32 = (const int*)eiv;
    const long long* __restrict__ p64 = (const long long*)eiv;
    int stride = gridDim.x * blockDim.x;
    for (int e = blockIdx.x * blockDim.x + threadIdx.x; e < E; e += stride) {
        int s, d;
        if (i32) { s = p32[e]; d = p32[E + e]; }
        else     { s = (int)p64[e]; d = (int)p64[(size_t)E + e]; }
        if ((unsigned)s >= N_NODES) s = 0;
        if ((unsigned)d >= N_NODES) d = 0;
        int pos = g_off[d] + g_bsum[d >> 8] + atomicAdd(&g_cur[d], 1);
        g_csr[pos] = s;
    }
}

// ---------------- GEMM: g_hs(fp16) = dinv[m] * (X[N,K] @ W[K,64]) -------------
template <int K, bool FROM_GX>
__global__ __launch_bounds__(256)
void k_gemm(const float* __restrict__ Xext, const float* __restrict__ W)
{
    const float* __restrict__ X = FROM_GX ? (const float*)g_x : Xext;

    constexpr int BM = 128, BN = 64, BK = 16;
    constexpr int XS = BM + 4;
    __shared__ float sbuf[BK * XS + BK * BN];
    float* Xs = sbuf;
    float* Ws = sbuf + BK * XS;

    const int tid = threadIdx.x;
    const int m0  = blockIdx.x * BM;
    const int tm  = tid >> 4;
    const int tn  = tid & 15;

    unsigned long long acc2[4][4];   // [row-pair][col]: lo=row 2rp, hi=row 2rp+1
#pragma unroll
    for (int rp = 0; rp < 4; rp++)
#pragma unroll
        for (int c = 0; c < 4; c++) acc2[rp][c] = 0ull;

    for (int k0 = 0; k0 < K; k0 += BK) {
#pragma unroll
        for (int p = 0; p < 2; p++) {
            int idx = tid + p * 256;
            int m = idx >> 2, kq = idx & 3;
            int gm = m0 + m;
            float4 v = make_float4(0.f, 0.f, 0.f, 0.f);
            if (gm < N_NODES)
                v = *(const float4*)(X + (size_t)gm * K + k0 + 4 * kq);
            Xs[(4 * kq + 0) * XS + m] = v.x;
            Xs[(4 * kq + 1) * XS + m] = v.y;
            Xs[(4 * kq + 2) * XS + m] = v.z;
            Xs[(4 * kq + 3) * XS + m] = v.w;
        }
        {
            int kk = tid >> 4, nq = tid & 15;
            *(float4*)(Ws + kk * BN + 4 * nq) =
                *(const float4*)(W + (size_t)(k0 + kk) * BN + 4 * nq);
        }
        __syncthreads();
#pragma unroll
        for (int kk = 0; kk < BK; kk++) {
            float a[8], b[4];
            *(float4*)&a[0] = *(const float4*)&Xs[kk * XS + 8 * tm];
            *(float4*)&a[4] = *(const float4*)&Xs[kk * XS + 8 * tm + 4];
            *(float4*)&b[0] = *(const float4*)&Ws[kk * BN + 4 * tn];
            unsigned long long a2[4], b2[4];
            PACK2(a2[0], a[0], a[1]);
            PACK2(a2[1], a[2], a[3]);
            PACK2(a2[2], a[4], a[5]);
            PACK2(a2[3], a[6], a[7]);
            PACK2(b2[0], b[0], b[0]);
            PACK2(b2[1], b[1], b[1]);
            PACK2(b2[2], b[2], b[2]);
            PACK2(b2[3], b[3], b[3]);
#pragma unroll
            for (int rp = 0; rp < 4; rp++)
#pragma unroll
                for (int c = 0; c < 4; c++)
                    FMA2(acc2[rp][c], a2[rp], b2[c]);
        }
        __syncthreads();
    }

#pragma unroll
    for (int rp = 0; rp < 4; rp++) {
        float lo[4], hi[4];
#pragma unroll
        for (int c = 0; c < 4; c++) UNPACK2(lo[c], hi[c], acc2[rp][c]);
        int mA = m0 + 8 * tm + 2 * rp;
        int mB = mA + 1;
        if (mA < N_NODES) {
            float dv = g_dinv[mA];
            __half2 h0 = __floats2half2_rn(dv * lo[0], dv * lo[1]);
            __half2 h1 = __floats2half2_rn(dv * lo[2], dv * lo[3]);
            uint2 u;
            u.x = *(unsigned*)&h0;
            u.y = *(unsigned*)&h1;
            *(uint2*)(g_hs + (size_t)mA * BN + 4 * tn) = u;
        }
        if (mB < N_NODES) {
            float dv = g_dinv[mB];
            __half2 h0 = __floats2half2_rn(dv * hi[0], dv * hi[1]);
            __half2 h1 = __floats2half2_rn(dv * hi[2], dv * hi[3]);
            uint2 u;
            u.x = *(unsigned*)&h0;
            u.y = *(unsigned*)&h1;
            *(uint2*)(g_hs + (size_t)mB * BN + 4 * tn) = u;
        }
    }
}

// ---------------- gather + finalize: g_x = relu(dinv*(Σ hs[nbr] + hs_i) + b) --
// 16 lanes per node; each lane owns 4 features = one uint2 (2×half2) per row.
__global__ __launch_bounds__(256)
void k_gather(const float* __restrict__ bias)
{
    int g = (blockIdx.x * 256 + threadIdx.x) >> 4;   // node id
    int l = threadIdx.x & 15;
    if (g >= N_NODES) return;

    const int beg = g_off[g] + g_bsum[g >> 8];
    const int deg = g_cnt[g];
    const int end = beg + deg;

    // self-loop term
    float4 acc;
    {
        uint2 u = *(const uint2*)(g_hs + (size_t)g * HF + 4 * l);
        float2 p0 = __half22float2(*(__half2*)&u.x);
        float2 p1 = __half22float2(*(__half2*)&u.y);
        acc = make_float4(p0.x, p0.y, p1.x, p1.y);
    }

    int j = beg;
    for (; j + 2 <= end; j += 2) {
        int s0 = g_csr[j];
        int s1 = g_csr[j + 1];
        uint2 u0 = *(const uint2*)(g_hs + (size_t)s0 * HF + 4 * l);
        uint2 u1 = *(const uint2*)(g_hs + (size_t)s1 * HF + 4 * l);
        float2 a0 = __half22float2(*(__half2*)&u0.x);
        float2 a1 = __half22float2(*(__half2*)&u0.y);
        float2 c0 = __half22float2(*(__half2*)&u1.x);
        float2 c1 = __half22float2(*(__half2*)&u1.y);
        acc.x += a0.x + c0.x;
        acc.y += a0.y + c0.y;
        acc.z += a1.x + c1.x;
        acc.w += a1.y + c1.y;
    }
    if (j < end) {
        int s0 = g_csr[j];
        uint2 u0 = *(const uint2*)(g_hs + (size_t)s0 * HF + 4 * l);
        float2 a0 = __half22float2(*(__half2*)&u0.x);
        float2 a1 = __half22float2(*(__half2*)&u0.y);
        acc.x += a0.x; acc.y += a0.y; acc.z += a1.x; acc.w += a1.y;
    }

    float dv = g_dinv[g];
    float4 b = *(const float4*)(bias + 4 * l);
    float4 o;
    o.x = fmaxf(fmaf(dv, acc.x, b.x), 0.f);
    o.y = fmaxf(fmaf(dv, acc.y, b.y), 0.f);
    o.z = fmaxf(fmaf(dv, acc.z, b.z), 0.f);
    o.w = fmaxf(fmaf(dv, acc.w, b.w), 0.f);
    *(float4*)(g_x + (size_t)g * HF + 4 * l) = o;
}

// ---------------- head GEMM: out[f*N+m] = sigmoid(g_x @ Wl + bl) -------------
__global__ __launch_bounds__(256)
void k_gemm_head(const float* __restrict__ W, const float* __restrict__ bias,
                 float* __restrict__ out)
{
    constexpr int K = 64, BM = 128, BN = 64, BK = 16;
    constexpr int XS = BM + 4;
    constexpr int SS = BN + 4;
    __shared__ float sbuf[BM * SS];
    float* Xs = sbuf;
    float* Ws = sbuf + BK * XS;

    const int tid = threadIdx.x;
    const int m0  = blockIdx.x * BM;
    const int tm  = tid >> 4;
    const int tn  = tid & 15;

    unsigned long long acc2[4][4];
#pragma unroll
    for (int rp = 0; rp < 4; rp++)
#pragma unroll
        for (int c = 0; c < 4; c++) acc2[rp][c] = 0ull;

    for (int k0 = 0; k0 < K; k0 += BK) {
#pragma unroll
        for (int p = 0; p < 2; p++) {
            int idx = tid + p * 256;
            int m = idx >> 2, kq = idx & 3;
            int gm = m0 + m;
            float4 v = make_float4(0.f, 0.f, 0.f, 0.f);
            if (gm < N_NODES)
                v = *(const float4*)(g_x + (size_t)gm * K + k0 + 4 * kq);
            Xs[(4 * kq + 0) * XS + m] = v.x;
            Xs[(4 * kq + 1) * XS + m] = v.y;
            Xs[(4 * kq + 2) * XS + m] = v.z;
            Xs[(4 * kq + 3) * XS + m] = v.w;
        }
        {
            int kk = tid >> 4, nq = tid & 15;
            *(float4*)(Ws + kk * BN + 4 * nq) =
                *(const float4*)(W + (size_t)(k0 + kk) * BN + 4 * nq);
        }
        __syncthreads();
#pragma unroll
        for (int kk = 0; kk < BK; kk++) {
            float a[8], b[4];
            *(float4*)&a[0] = *(const float4*)&Xs[kk * XS + 8 * tm];
            *(float4*)&a[4] = *(const float4*)&Xs[kk * XS + 8 * tm + 4];
            *(float4*)&b[0] = *(const float4*)&Ws[kk * BN + 4 * tn];
            unsigned long long a2[4], b2[4];
            PACK2(a2[0], a[0], a[1]);
            PACK2(a2[1], a[2], a[3]);
            PACK2(a2[2], a[4], a[5]);
            PACK2(a2[3], a[6], a[7]);
            PACK2(b2[0], b[0], b[0]);
            PACK2(b2[1], b[1], b[1]);
            PACK2(b2[2], b[2], b[2]);
            PACK2(b2[3], b[3], b[3]);
#pragma unroll
            for (int rp = 0; rp < 4; rp++)
#pragma unroll
                for (int c = 0; c < 4; c++)
                    FMA2(acc2[rp][c], a2[rp], b2[c]);
        }
        __syncthreads();
    }

    float b4[4];
    *(float4*)b4 = *(const float4*)(bias + 4 * tn);
#pragma unroll
    for (int rp = 0; rp < 4; rp++) {
        float lo[4], hi[4];
#pragma unroll
        for (int c = 0; c < 4; c++) UNPACK2(lo[c], hi[c], acc2[rp][c]);
        int mlocA = 8 * tm + 2 * rp;
        float4 vA, vB;
        float t;
        t = lo[0] + b4[0]; vA.x = 1.f / (1.f + __expf(-t));
        t = lo[1] + b4[1]; vA.y = 1.f / (1.f + __expf(-t));
        t = lo[2] + b4[2]; vA.z = 1.f / (1.f + __expf(-t));
        t = lo[3] + b4[3]; vA.w = 1.f / (1.f + __expf(-t));
        t = hi[0] + b4[0]; vB.x = 1.f / (1.f + __expf(-t));
        t = hi[1] + b4[1]; vB.y = 1.f / (1.f + __expf(-t));
        t = hi[2] + b4[2]; vB.z = 1.f / (1.f + __expf(-t));
        t = hi[3] + b4[3]; vB.w = 1.f / (1.f + __expf(-t));
        *(float4*)&sbuf[mlocA * SS + 4 * tn] = vA;
        *(float4*)&sbuf[(mlocA + 1) * SS + 4 * tn] = vB;
    }
    __syncthreads();
    for (int idx = tid; idx < BM * BN; idx += 256) {
        int f = idx >> 7;
        int mloc = idx & 127;
        int m = m0 + mloc;
        if (m < N_NODES)
            out[(size_t)f * N_NODES + m] = sbuf[mloc * SS + f];
    }
}

// ---------------- launch ------------------------------------------------------
extern "C" void kernel_launch(void* const* d_in, const int* in_sizes, int n_in,
                              void* d_out, int out_size)
{
    const float* x  = (const float*)d_in[0];
    const void*  ei = d_in[1];
    const float* W1 = (const float*)d_in[2];
    const float* b1 = (const float*)d_in[3];
    const float* W2 = (const float*)d_in[4];
    const float* b2 = (const float*)d_in[5];
    const float* Wl = (const float*)d_in[6];
    const float* bl = (const float*)d_in[7];
    float*       out = (float*)d_out;
    const int nwords = in_sizes[1];
    const int E = nwords / 2;

    const int nblk = NBLK_SCAN;                           // 391
    const int gemm_blocks = (N_NODES + 127) / 128;        // 782
    const int gather_blocks = (N_NODES * 16 + 255) / 256; // 6250

    // ---- graph prep (5 kernels) ----
    k_init<<<nblk, 256>>>((const int*)ei, nwords);   // launch 0
    k_prep<<<2048, 256>>>(ei, E);                    // launch 1
    k_scan1<<<nblk, 256>>>();                        // launch 2 (+dinv)
    k_scan2<<<1, 512>>>();                           // launch 3
    k_fill<<<2048, 256>>>(ei, E);                    // launch 4

    // ---- layer 1 ----
    k_gemm<128, false><<<gemm_blocks, 256>>>(x, W1); // launch 5 (ncu window)
    k_gather<<<gather_blocks, 256>>>(b1);            // launch 6

    // ---- layer 2 ----
    k_gemm<64, true><<<gemm_blocks, 256>>>(nullptr, W2);
    k_gather<<<gather_blocks, 256>>>(b2);

    // ---- head: sigmoid(g_x @ Wl + bl), transposed store ----
    k_gemm_head<<<gemm_blocks, 256>>>(Wl, bl, out);

    (void)n_in; (void)out_size;
}

// round 8
// speedup vs baseline: 3.3519x; 1.0985x over previous
#include <cuda_runtime.h>
#include <cuda_fp16.h>
#include <cstdint>

#define N_NODES 100000
#define HF 64
#define E_MAX 1600000
#define NBLK_SCAN 391            // ceil(N_NODES/256)

// ---------------- scratch (static device globals; no allocation) -------------
__device__ __align__(16) __half g_hs[N_NODES * HF];  // dinv-scaled features, fp16
__device__ __align__(16) __half g_x[N_NODES * HF];   // layer activations, fp16
__device__ float g_dinv[N_NODES];
__device__ int   g_cnt[N_NODES];      // in-degree (no self loop)
__device__ int   g_off[N_NODES];      // block-local exclusive prefix of cnt
__device__ int   g_cur[N_NODES];      // fill cursors
__device__ int   g_bsum[512];         // per-block offsets (final after scan2)
__device__ int   g_csr[E_MAX];        // src ids sorted by dst
__device__ int   g_is_i32 = 0;        // monotone OR; deterministic across replays

// ---------------- prep -------------------------------------------------------
__global__ void k_init(const int* __restrict__ ei32, int nwords) {
    int i = blockIdx.x * 256 + threadIdx.x;
    if (i < N_NODES) { g_cnt[i] = 0; g_cur[i] = 0; }
    int w = 2 * i + 1;   // odd words: int64 high-halves are 0, int32 data isn't
    if (i < 2048 && w < nwords) {
        if (ei32[w] != 0) atomicOr(&g_is_i32, 1);
    }
}

__global__ void k_prep(const void* __restrict__ eiv, int E) {
    const bool i32 = (g_is_i32 != 0);
    const int* __restrict__ p32 = (const int*)eiv;
    const long long* __restrict__ p64 = (const long long*)eiv;
    int stride = gridDim.x * blockDim.x;
    for (int i = blockIdx.x * blockDim.x + threadIdx.x; i < E; i += stride) {
        int d = i32 ? p32[E + i] : (int)p64[(size_t)E + i];
        if ((unsigned)d >= N_NODES) d = 0;
        atomicAdd(&g_cnt[d], 1);
    }
}

__global__ __launch_bounds__(256) void k_scan1() {
    __shared__ int sh[256];
    int i = blockIdx.x * 256 + threadIdx.x;
    int c = (i < N_NODES) ? g_cnt[i] : 0;
    sh[threadIdx.x] = c;
    __syncthreads();
    int v = c;
#pragma unroll
    for (int ofs = 1; ofs < 256; ofs <<= 1) {
        int t = (threadIdx.x >= ofs) ? sh[threadIdx.x - ofs] : 0;
        __syncthreads();
        v += t;
        sh[threadIdx.x] = v;
        __syncthreads();
    }
    if (i < N_NODES) {
        g_off[i] = v - c;
        g_dinv[i] = rsqrtf((float)c + 1.0f);
    }
    if (threadIdx.x == 255) g_bsum[blockIdx.x] = v;
}

__global__ __launch_bounds__(512) void k_scan2() {
    __shared__ int sh[512];
    int t = threadIdx.x;
    int c = (t < NBLK_SCAN) ? g_bsum[t] : 0;
    sh[t] = c;
    __syncthreads();
    int v = c;
#pragma unroll
    for (int ofs = 1; ofs < 512; ofs <<= 1) {
        int x = (t >= ofs) ? sh[t - ofs] : 0;
        __syncthreads();
        v += x;
        sh[t] = v;
        __syncthreads();
    }
    if (t < NBLK_SCAN) g_bsum[t] = v - c;
}

__global__ __launch_bounds__(256) void k_fill(const void* __restrict__ eiv, int E) {
    const bool i32 = (g_is_i32 != 0);
    const int* __restrict__ p32 = (const int*)eiv;
    const long long* __restrict__ p64 = (const long long*)eiv;
    int stride = gridDim.x * blockDim.x;
    for (int e = blockIdx.x * blockDim.x + threadIdx.x; e < E; e += stride) {
        int s, d;
        if (i32) { s = p32[e]; d = p32[E + e]; }
        else     { s = (int)p64[e]; d = (int)p64[(size_t)E + e]; }
        if ((unsigned)s >= N_NODES) s = 0;
        if ((unsigned)d >= N_NODES) d = 0;
        int pos = g_off[d] + g_bsum[d >> 8] + atomicAdd(&g_cur[d], 1);
        g_csr[pos] = s;
    }
}

// ---------------- tensor-core GEMM ------------------------------------------
// C[M,64] = X[M,K] @ W[K,64] via mma.sync m16n8k16 (fp16 in, fp32 accum)
// HEAD=0: g_hs[m][f] = half(dinv[m] * C)          (XHALF: X = g_x fp16)
// HEAD=1: out[f*N+m] = sigmoid(C + bias[f])       (transposed via smem staging)
#define MMA16816(d0,d1,d2,d3,a0,a1,a2,a3,b0,b1)                          \
    asm volatile("mma.sync.aligned.m16n8k16.row.col.f32.f16.f16.f32 "   \
                 "{%0,%1,%2,%3},{%4,%5,%6,%7},{%8,%9},{%0,%1,%2,%3};"   \
                 : "+f"(d0), "+f"(d1), "+f"(d2), "+f"(d3)               \
                 : "r"(a0), "r"(a1), "r"(a2), "r"(a3), "r"(b0), "r"(b1))

template <int K, bool XHALF, bool HEAD>
__global__ __launch_bounds__(256)
void k_mma(const float* __restrict__ Xf, const float* __restrict__ W,
           const float* __restrict__ bias, float* __restrict__ out)
{
    constexpr int BM = 128, BK = 64;
    constexpr int XSTR = 72;     // halves; bank-conflict-free fragment loads
    constexpr int WSTR = 136;
    __shared__ __align__(16) char sraw[BM * XSTR * 2 + 64 * WSTR * 2]; // 35840 B
    __half* Xs = (__half*)sraw;                       // [128][72]
    __half* Wt = (__half*)(sraw + BM * XSTR * 2);     // [64][136], Wt[n][k]=W[k][n]
    float*  stg = (float*)sraw;                       // head staging [128][68]

    const int tid  = threadIdx.x;
    const int w    = tid >> 5;
    const int lane = tid & 31;
    const int m0   = blockIdx.x * BM;
    const int r    = lane >> 2;   // group id 0..7
    const int q    = lane & 3;    // thread-in-group

    // stage W transposed as fp16 (one-time, tiny)
    for (int idx = tid; idx < K * 64; idx += 256) {
        int k = idx >> 6, n = idx & 63;
        Wt[n * WSTR + k] = __float2half(W[idx]);
    }

    float acc[8][4];
#pragma unroll
    for (int j = 0; j < 8; j++) {
        acc[j][0] = acc[j][1] = acc[j][2] = acc[j][3] = 0.f;
    }

    for (int k0 = 0; k0 < K; k0 += BK) {
        if (XHALF) {
            // X = g_x, fp16 [m][64]; K==64 so one chunk, straight uint4 copy
            for (int idx = tid; idx < BM * 8; idx += 256) {
                int m = idx >> 3, c = idx & 7;
                int gm = m0 + m;
                uint4 v = make_uint4(0, 0, 0, 0);
                if (gm < N_NODES)
                    v = *(const uint4*)((const __half*)g_x + (size_t)gm * 64 + 8 * c);
                *(uint4*)(Xs + m * XSTR + 8 * c) = v;
            }
        } else {
            // X fp32 -> fp16 chunk [128][64]
            for (int idx = tid; idx < BM * 32; idx += 256) {
                int m = idx >> 5, c = idx & 31;
                int gm = m0 + m;
                __half2 h = __floats2half2_rn(0.f, 0.f);
                if (gm < N_NODES) {
                    float2 v = *(const float2*)(Xf + (size_t)gm * K + k0 + 2 * c);
                    h = __floats2half2_rn(v.x, v.y);
                }
                *(__half2*)(Xs + m * XSTR + 2 * c) = h;
            }
        }
        __syncthreads();
#pragma unroll
        for (int kc = 0; kc < BK; kc += 16) {
            unsigned a0, a1, a2, a3;
            const __half* Ab = Xs + (16 * w + r) * XSTR + kc + 2 * q;
            a0 = *(const unsigned*)(Ab);
            a1 = *(const unsigned*)(Ab + 8 * XSTR);
            a2 = *(const unsigned*)(Ab + 8);
            a3 = *(const unsigned*)(Ab + 8 * XSTR + 8);
#pragma unroll
            for (int j = 0; j < 8; j++) {
                const __half* Bb = Wt + (8 * j + r) * WSTR + (k0 + kc) + 2 * q;
                unsigned b0 = *(const unsigned*)(Bb);
                unsigned b1 = *(const unsigned*)(Bb + 8);
                MMA16816(acc[j][0], acc[j][1], acc[j][2], acc[j][3],
                         a0, a1, a2, a3, b0, b1);
            }
        }
        __syncthreads();
    }

    if (!HEAD) {
        int row0 = m0 + 16 * w + r;
        int row1 = row0 + 8;
        if (row0 < N_NODES) {
            float dv = g_dinv[row0];
#pragma unroll
            for (int j = 0; j < 8; j++) {
                __half2 h = __floats2half2_rn(dv * acc[j][0], dv * acc[j][1]);
                *(__half2*)(g_hs + (size_t)row0 * 64 + 8 * j + 2 * q) = h;
            }
        }
        if (row1 < N_NODES) {
            float dv = g_dinv[row1];
#pragma unroll
            for (int j = 0; j < 8; j++) {
                __half2 h = __floats2half2_rn(dv * acc[j][2], dv * acc[j][3]);
                *(__half2*)(g_hs + (size_t)row1 * 64 + 8 * j + 2 * q) = h;
            }
        }
    } else {
        // stage sigmoid(C + bias) into smem, then coalesced transposed write
        constexpr int SS = 68;
        int rl0 = 16 * w + r;
        int rl1 = rl0 + 8;
#pragma unroll
        for (int j = 0; j < 8; j++) {
            int col = 8 * j + 2 * q;
            float bx = bias[col], by = bias[col + 1];
            stg[rl0 * SS + col]     = 1.f / (1.f + __expf(-(acc[j][0] + bx)));
            stg[rl0 * SS + col + 1] = 1.f / (1.f + __expf(-(acc[j][1] + by)));
            stg[rl1 * SS + col]     = 1.f / (1.f + __expf(-(acc[j][2] + bx)));
            stg[rl1 * SS + col + 1] = 1.f / (1.f + __expf(-(acc[j][3] + by)));
        }
        __syncthreads();
        for (int idx = tid; idx < BM * 64; idx += 256) {
            int f = idx >> 7;
            int ml = idx & 127;
            int m = m0 + ml;
            if (m < N_NODES)
                out[(size_t)f * N_NODES + m] = stg[ml * SS + f];
        }
    }
}

// ---------------- gather + finalize: g_x = relu(dinv*(Σ hs[nbr] + hs_i) + b) --
__global__ __launch_bounds__(256)
void k_gather(const float* __restrict__ bias)
{
    int g = (blockIdx.x * 256 + threadIdx.x) >> 4;   // node id
    int l = threadIdx.x & 15;
    if (g >= N_NODES) return;

    const int beg = g_off[g] + g_bsum[g >> 8];
    const int deg = g_cnt[g];
    const int end = beg + deg;

    float4 acc;
    {
        uint2 u = *(const uint2*)(g_hs + (size_t)g * HF + 4 * l);
        float2 p0 = __half22float2(*(__half2*)&u.x);
        float2 p1 = __half22float2(*(__half2*)&u.y);
        acc = make_float4(p0.x, p0.y, p1.x, p1.y);
    }

    int j = beg;
    for (; j + 2 <= end; j += 2) {
        int s0 = g_csr[j];
        int s1 = g_csr[j + 1];
        uint2 u0 = *(const uint2*)(g_hs + (size_t)s0 * HF + 4 * l);
        uint2 u1 = *(const uint2*)(g_hs + (size_t)s1 * HF + 4 * l);
        float2 a0 = __half22float2(*(__half2*)&u0.x);
        float2 a1 = __half22float2(*(__half2*)&u0.y);
        float2 c0 = __half22float2(*(__half2*)&u1.x);
        float2 c1 = __half22float2(*(__half2*)&u1.y);
        acc.x += a0.x + c0.x;
        acc.y += a0.y + c0.y;
        acc.z += a1.x + c1.x;
        acc.w += a1.y + c1.y;
    }
    if (j < end) {
        int s0 = g_csr[j];
        uint2 u0 = *(const uint2*)(g_hs + (size_t)s0 * HF + 4 * l);
        float2 a0 = __half22float2(*(__half2*)&u0.x);
        float2 a1 = __half22float2(*(__half2*)&u0.y);
        acc.x += a0.x; acc.y += a0.y; acc.z += a1.x; acc.w += a1.y;
    }

    float dv = g_dinv[g];
    float4 b = *(const float4*)(bias + 4 * l);
    float ox = fmaxf(fmaf(dv, acc.x, b.x), 0.f);
    float oy = fmaxf(fmaf(dv, acc.y, b.y), 0.f);
    float oz = fmaxf(fmaf(dv, acc.z, b.z), 0.f);
    float ow = fmaxf(fmaf(dv, acc.w, b.w), 0.f);
    __half2 h0 = __floats2half2_rn(ox, oy);
    __half2 h1 = __floats2half2_rn(oz, ow);
    uint2 u;
    u.x = *(unsigned*)&h0;
    u.y = *(unsigned*)&h1;
    *(uint2*)(g_x + (size_t)g * HF + 4 * l) = u;
}

// ---------------- launch ------------------------------------------------------
extern "C" void kernel_launch(void* const* d_in, const int* in_sizes, int n_in,
                              void* d_out, int out_size)
{
    const float* x  = (const float*)d_in[0];
    const void*  ei = d_in[1];
    const float* W1 = (const float*)d_in[2];
    const float* b1 = (const float*)d_in[3];
    const float* W2 = (const float*)d_in[4];
    const float* b2 = (const float*)d_in[5];
    const float* Wl = (const float*)d_in[6];
    const float* bl = (const float*)d_in[7];
    float*       out = (float*)d_out;
    const int nwords = in_sizes[1];
    const int E = nwords / 2;

    const int nblk = NBLK_SCAN;                           // 391
    const int gemm_blocks = (N_NODES + 127) / 128;        // 782
    const int gather_blocks = (N_NODES * 16 + 255) / 256; // 6250

    // ---- graph prep ----
    k_init<<<nblk, 256>>>((const int*)ei, nwords);
    k_prep<<<2048, 256>>>(ei, E);
    k_scan1<<<nblk, 256>>>();
    k_scan2<<<1, 512>>>();
    k_fill<<<2048, 256>>>(ei, E);

    // ---- layer 1 ----
    k_mma<128, false, false><<<gemm_blocks, 256>>>(x, W1, nullptr, nullptr);
    k_gather<<<gather_blocks, 256>>>(b1);

    // ---- layer 2 ----
    k_mma<64, true, false><<<gemm_blocks, 256>>>(nullptr, W2, nullptr, nullptr);
    k_gather<<<gather_blocks, 256>>>(b2);

    // ---- head: sigmoid(g_x @ Wl + bl), transposed store ----
    k_mma<64, true, true><<<gemm_blocks, 256>>>(nullptr, Wl, bl, out);

    (void)n_in; (void)out_size;
}